// round 11
// baseline (speedup 1.0000x reference)
#include <cuda_runtime.h>
#include <math.h>

#define NB     256
#define NPB    65536
#define NBATCH 4
#define EPS    1e-10f
#define INV_N  (1.0f / 65536.0f)

// ---------- persistent scratch (zero-init at load; re-zeroed every call) ----------
// Slot-shifted joint: J2[b][i][j][0] feeds cell (i,j), J2[b][i][j][1] feeds (i,j+1).
__device__ float  g_J2[NBATCH][NB][NB][2];     // 2 MB
__device__ float  g_h1[NBATCH * NB];
__device__ float  g_h2[NBATCH * NB];
__device__ double g_sj[NBATCH];
__device__ double g_ej[NBATCH];
__device__ float  g_H1[NBATCH], g_H2[NBATCH];
__device__ unsigned g_bar1;

__device__ __forceinline__ void red2(float* p, float a, float b) {
    asm volatile("red.global.add.v2.f32 [%0], {%1, %2};"
                 :: "l"(p), "f"(a), "f"(b) : "memory");
}

// ================= kernel 1: sparse KDE accumulation =================
// sigma=0.1 in bin units: only the two straddling bins carry weight (third
// bin <= e^-50 ~ 2e-22 relative). Joint: 2 aligned red.v2 per pixel (the
// LTS-atomic-ALU floor for this layout). Marginals: shared-memory atomics.
// Ends with an explicit PDL trigger so the reduce grid launches as soon as
// all CTAs' work is issued, not after kernel teardown.
#define THREADS_ACC 256
#define PIX_PER_CTA 1024

__global__ __launch_bounds__(THREADS_ACC)
void mi_accum_kernel(const float* __restrict__ in1, const float* __restrict__ in2) {
    __shared__ float sh1[NB];
    __shared__ float sh2[NB];
    int tid = threadIdx.x;
    int base = blockIdx.x * PIX_PER_CTA;
    int b = base >> 16;

    float4 a = ((const float4*)(in1 + base))[tid];
    float4 c = ((const float4*)(in2 + base))[tid];

    sh1[tid] = 0.0f;
    sh2[tid] = 0.0f;
    __syncthreads();

    const float xs1[4] = {a.x, a.y, a.z, a.w};
    const float xs2[4] = {c.x, c.y, c.z, c.w};

#pragma unroll
    for (int k = 0; k < 4; k++) {
        float x1 = xs1[k] * 255.0f;
        float x2 = xs2[k] * 255.0f;
        int i0 = min((int)floorf(x1), NB - 2);
        int j0 = min((int)floorf(x2), NB - 2);
        float f1 = x1 - (float)i0, q1 = 1.0f - f1;
        float f2 = x2 - (float)j0, q2 = 1.0f - f2;
        float wa1 = __expf(-50.0f * f1 * f1);
        float wb1 = __expf(-50.0f * q1 * q1);
        float wa2 = __expf(-50.0f * f2 * f2);
        float wb2 = __expf(-50.0f * q2 * q2);

        red2(&g_J2[b][i0][j0][0],     wa1 * wa2, wa1 * wb2);
        red2(&g_J2[b][i0 + 1][j0][0], wb1 * wa2, wb1 * wb2);

        atomicAdd(&sh1[i0],     wa1);
        atomicAdd(&sh1[i0 + 1], wb1);
        atomicAdd(&sh2[j0],     wa2);
        atomicAdd(&sh2[j0 + 1], wb2);
    }

    __syncthreads();
    atomicAdd(&g_h1[b * NB + tid], sh1[tid]);
    atomicAdd(&g_h2[b * NB + tid], sh2[tid]);

    // explicit PDL trigger: all our memory ops are ordered before it
    __threadfence();
    asm volatile("griddepcontrol.launch_dependents;" ::: "memory");
}

// ================= kernel 2: PDL reduce + combine + re-zero =================
// merged float2 block reduction over 256 threads (one set of barriers)
__device__ __forceinline__ float2 fred256x2(float va, float vb, float2* sred) {
#pragma unroll
    for (int o = 16; o; o >>= 1) {
        va += __shfl_xor_sync(0xffffffffu, va, o);
        vb += __shfl_xor_sync(0xffffffffu, vb, o);
    }
    int wid = threadIdx.x >> 5, lid = threadIdx.x & 31;
    if (lid == 0) sred[wid] = make_float2(va, vb);
    __syncthreads();
    if (threadIdx.x < 32) {
        float ra = (threadIdx.x < 8) ? sred[threadIdx.x].x : 0.0f;
        float rb = (threadIdx.x < 8) ? sred[threadIdx.x].y : 0.0f;
#pragma unroll
        for (int o = 4; o; o >>= 1) {
            ra += __shfl_xor_sync(0xffffffffu, ra, o);
            rb += __shfl_xor_sync(0xffffffffu, rb, o);
        }
        if (threadIdx.x == 0) sred[0] = make_float2(ra, rb);
    }
    __syncthreads();
    float2 out = sred[0];
    __syncthreads();
    return out;
}

__global__ __launch_bounds__(256)
void mi_reduce_final_kernel(float* __restrict__ out) {
    __shared__ float2 sred[8];
    int tid = threadIdx.x;
    int rb  = blockIdx.x >> 6;
    int sub = blockIdx.x & 63;

    int row   = 4 * sub + (tid >> 6);
    int cell0 = (tid & 63) * 4;
    float* rowp = &g_J2[rb][row][0][0];      // 512 floats per row

    // ---- wait for accum's trigger (PDL); no-op under plain launch ----
    asm volatile("griddepcontrol.wait;" ::: "memory");

    float4 p0 = *(float4*)(rowp + cell0 * 2);        // slots c0, c0+1
    float4 p1 = *(float4*)(rowp + cell0 * 2 + 4);    // slots c0+2, c0+3
    // prev = [c0-1][1] = previous thread's p1.w (lanes are consecutive cells)
    float prev = __shfl_up_sync(0xffffffffu, p1.w, 1);
    if ((tid & 63) == 0) prev = 0.0f;        // first 4-cell group of the row
    if ((tid & 31) == 0 && (tid & 63) != 0)  // lane 0 of odd warp-half: cross-warp
        prev = rowp[cell0 * 2 - 1];

    __syncthreads();                          // all reads before any zeroing
    *(float4*)(rowp + cell0 * 2)     = make_float4(0.f, 0.f, 0.f, 0.f);
    *(float4*)(rowp + cell0 * 2 + 4) = make_float4(0.f, 0.f, 0.f, 0.f);

    float v0 = p0.x + prev;
    float v1 = p0.z + p0.y;
    float v2 = p1.x + p0.w;
    float v3 = p1.z + p1.y;                   // p1.w feeds next thread's v0

    float sj = (v0 + v1) + (v2 + v3);
    float ej = v0 * __log2f(v0 + EPS)
             + v1 * __log2f(v1 + EPS)
             + v2 * __log2f(v2 + EPS)
             + v3 * __log2f(v3 + EPS);

    float2 se = fred256x2(sj, ej, sred);
    if (tid == 0) {
        atomicAdd(&g_sj[rb], (double)se.x);
        atomicAdd(&g_ej[rb], (double)se.y);
    }

    // marginals: exact reference math, one CTA per batch
    if (sub == 0) {
        float h1 = __ldcg(&g_h1[rb * NB + tid]);
        float h2 = __ldcg(&g_h2[rb * NB + tid]);
        g_h1[rb * NB + tid] = 0.0f;           // same-thread read-then-zero
        g_h2[rb * NB + tid] = 0.0f;
        float m1 = h1 * INV_N;
        float m2 = h2 * INV_N;
        float2 S = fred256x2(m1, m2, sred);
        float p1v = m1 / (S.x + EPS);
        float p2v = m2 / (S.y + EPS);
        float2 E = fred256x2(p1v * __log2f(p1v + EPS),
                             p2v * __log2f(p2v + EPS), sred);
        if (tid == 0) { g_H1[rb] = -E.x; g_H2[rb] = -E.y; }
    }

    // last-block combine + reset
    __threadfence();
    __syncthreads();
    if (tid == 0) {
        unsigned t = atomicAdd(&g_bar1, 1u);
        if (t == 255u) {
            __threadfence();
            double acc = 0.0;
#pragma unroll
            for (int bb = 0; bb < NBATCH; bb++) {
                double Sj = g_sj[bb];
                double Ej = g_ej[bb];
                double den = Sj + (double)EPS;
                // Hj = -sum q*log2(q+eps), q=j/(Sj+eps), factored single-pass
                double Hj = -(Ej - Sj * log2(den)) / den;
                double H1 = (double)g_H1[bb];
                double H2 = (double)g_H2[bb];
                acc += 2.0 * (H1 + H2 - Hj) / (H1 + H2);
                g_sj[bb] = 0.0; g_ej[bb] = 0.0;
                g_H1[bb] = 0.0f; g_H2[bb] = 0.0f;
            }
            out[0] = (float)(acc * 0.25);
            g_bar1 = 0u;
        }
    }
}

// ================= launch: 2 kernels, second via PDL =================
extern "C" void kernel_launch(void* const* d_in, const int* in_sizes, int n_in,
                              void* d_out, int out_size) {
    const float* in1 = (const float*)d_in[0];
    const float* in2 = (const float*)d_in[1];
    float* out = (float*)d_out;

    mi_accum_kernel<<<(NBATCH * NPB) / PIX_PER_CTA, THREADS_ACC>>>(in1, in2);

    cudaLaunchConfig_t cfg = {};
    cfg.gridDim  = dim3(256, 1, 1);
    cfg.blockDim = dim3(256, 1, 1);
    cudaLaunchAttribute attr[1];
    attr[0].id = cudaLaunchAttributeProgrammaticStreamSerialization;
    attr[0].val.programmaticStreamSerializationAllowed = 1;
    cfg.attrs = attr;
    cfg.numAttrs = 1;
    cudaError_t e = cudaLaunchKernelEx(&cfg, mi_reduce_final_kernel, out);
    if (e != cudaSuccess) {
        // PDL rejected -> plain launch fallback
        mi_reduce_final_kernel<<<256, 256>>>(out);
    }
}